// round 10
// baseline (speedup 1.0000x reference)
#include <cuda_runtime.h>
#include <cstdint>

#define D   128   // LATDIM
#define AA  64    // ANCHOR_SET_NUM
#define MT  64    // n rows per tile
#define RW  8     // rows per k_pre tile
#define SDS 72    // sd stride (words); 72 % 32 == 8 -> conflict-free fragments
#define SVS 136   // sv stride (words); 136 % 32 == 8
#define SAS 132   // acc stride (words)

// __device__ scratch (allocation-free rule)
__device__ float g_V[AA * D];       // [a][o]
__device__ float g_C[10048 * D];    // [t][o]

// ---------------------------------------------------------------------------
// packed f32x2 helpers (k_pre)
// ---------------------------------------------------------------------------
__device__ __forceinline__ unsigned long long pk2(float x, float y) {
    unsigned long long r;
    asm("mov.b64 %0, {%1, %2};" : "=l"(r) : "f"(x), "f"(y));
    return r;
}
__device__ __forceinline__ void unpk2(unsigned long long v, float& x, float& y) {
    asm("mov.b64 {%0, %1}, %2;" : "=f"(x), "=f"(y) : "l"(v));
}
__device__ __forceinline__ void ffma2(unsigned long long& a,
                                      unsigned long long b, unsigned long long c) {
    asm("fma.rn.f32x2 %0, %1, %2, %0;" : "+l"(a) : "l"(b), "l"(c));
}
__device__ __forceinline__ void fadd2(unsigned long long& a, unsigned long long b) {
    asm("add.rn.f32x2 %0, %0, %1;" : "+l"(a) : "l"(b));
}

// ---------------------------------------------------------------------------
// tf32 helpers (sm_80+ -> valid under compute_103)
// ---------------------------------------------------------------------------
__device__ __forceinline__ uint32_t f2tf32(float f) {
    uint32_t r;
    asm("cvt.rna.tf32.f32 %0, %1;" : "=r"(r) : "f"(f));
    return r;
}
__device__ __forceinline__ void mma_tf32(float& c0, float& c1, float& c2, float& c3,
                                         uint32_t a0, uint32_t a1, uint32_t a2,
                                         uint32_t a3, uint32_t b0, uint32_t b1) {
    asm("mma.sync.aligned.m16n8k8.row.col.f32.tf32.tf32.f32 "
        "{%0,%1,%2,%3}, {%4,%5,%6,%7}, {%8,%9}, {%0,%1,%2,%3};"
        : "+f"(c0), "+f"(c1), "+f"(c2), "+f"(c3)
        : "r"(a0), "r"(a1), "r"(a2), "r"(a3), "r"(b0), "r"(b1));
}

// ---------------------------------------------------------------------------
// k_pre (unchanged; proven through R7-R9):
//   C[t][o] = (1/A) * sum_k E2[t][k] * W[o][D+k] + b[o]
//   V[a][o] = (1/A) * sum_k embeds[anchor[a]][k] * W[o][k]
// ---------------------------------------------------------------------------
__global__ __launch_bounds__(1024)
void k_pre(const float* __restrict__ embeds,
           const float* __restrict__ W,
           const float* __restrict__ b,
           const int*   __restrict__ anchor,
           int N, int T, int nC) {
    extern __shared__ __align__(16) float sm[];
    float (*Wc)[32][129] = (float(*)[32][129])sm;            // [4][32][129]
    float (*XT)[8]       = (float(*)[8])(sm + 4 * 32 * 129);
    float* sch           = sm + 4 * 32 * 129 + D * 8;        // [11][2][128]
    unsigned long long* spart = (unsigned long long*)sch;    // overlay after gemm

    const int tid  = threadIdx.x;
    const int w    = tid >> 5;
    const int l    = tid & 31;
    const bool isV = (blockIdx.x >= nC);
    const int  t0  = isV ? (blockIdx.x - nC) * RW : blockIdx.x * RW;
    const int  R   = isV ? RW : min(RW, T - t0);
    const int  woff = isV ? 0 : D;

    // stage all 4 W chunks (transposed, coalesced)
    {
        const int orow = tid >> 3;
        const int kq   = (tid & 7) * 4;
        #pragma unroll
        for (int kc = 0; kc < 4; kc++) {
            const float4 wv = __ldg((const float4*)
                &W[(size_t)orow * (2 * D) + woff + kc * 32 + kq]);
            Wc[kc][kq + 0][orow] = wv.x;
            Wc[kc][kq + 1][orow] = wv.y;
            Wc[kc][kq + 2][orow] = wv.z;
            Wc[kc][kq + 3][orow] = wv.w;
        }
    }

    // build XT[k][r]
    if (isV) {
        const int k = tid & 127, r = tid >> 7;
        XT[k][r] = __ldg(&embeds[(size_t)__ldg(&anchor[t0 + r]) * D + k]);
    } else {
        const int ch = w >> 1, half = w & 1;
        if (ch < R + 3) {
            const int rbase = 16 * (t0 + ch) + 8 * half;
            float4 acc = {0.f, 0.f, 0.f, 0.f};
            #pragma unroll
            for (int i = 0; i < 8; i++) {
                int r = rbase + i; if (r >= N) r -= N;
                const float4 v = __ldg((const float4*)&embeds[(size_t)r * D + 4 * l]);
                acc.x += v.x; acc.y += v.y; acc.z += v.z; acc.w += v.w;
            }
            *(float4*)&sch[(ch * 2 + half) * 128 + 4 * l] = acc;
        }
        __syncthreads();
        const int k = tid & 127, r = tid >> 7;
        float val = 0.f;
        if (r < R) {
            #pragma unroll
            for (int c = 0; c < 4; c++)
                val += sch[((r + c) * 2 + 0) * 128 + k]
                     + sch[((r + c) * 2 + 1) * 128 + k];
        }
        XT[k][r] = val;
    }
    __syncthreads();

    // gemm: thread (o, rq, h)
    const int o  = tid & 127;
    const int rq = (tid >> 7) & 1;
    const int h  = tid >> 8;
    unsigned long long a0 = 0ull, a1 = 0ull;

    #pragma unroll
    for (int kk = 0; kk < 32; kk++) {
        const float wv = Wc[h][kk][o];
        const ulonglong2 x = *(const ulonglong2*)&XT[h * 32 + kk][4 * rq];
        const unsigned long long ww = pk2(wv, wv);
        ffma2(a0, x.x, ww);
        ffma2(a1, x.y, ww);
    }
    __syncthreads();

    if (h > 0) {
        ulonglong2 t; t.x = a0; t.y = a1;
        *(ulonglong2*)&spart[(((h - 1) * 256) + o * 2 + rq) * 2] = t;
    }
    __syncthreads();

    if (h == 0) {
        #pragma unroll
        for (int hh = 0; hh < 3; hh++) {
            const ulonglong2 t =
                *(const ulonglong2*)&spart[((hh * 256) + o * 2 + rq) * 2];
            fadd2(a0, t.x); fadd2(a1, t.y);
        }
        float r0, r1, r2, r3;
        unpk2(a0, r0, r1); unpk2(a1, r2, r3);
        float res[4] = {r0, r1, r2, r3};
        const float sc = 1.0f / AA;
        if (isV) {
            #pragma unroll
            for (int i = 0; i < 4; i++)
                g_V[(t0 + 4 * rq + i) * D + o] = res[i] * sc;
        } else {
            const float bias = __ldg(&b[o]);
            #pragma unroll
            for (int i = 0; i < 4; i++) {
                const int row = 4 * rq + i;
                if (row < R)
                    g_C[(size_t)(t0 + row) * D + o] = res[i] * sc + bias;
            }
        }
    }
}

// ---------------------------------------------------------------------------
// k_main_mma v2: tf32 mma.sync, grid=148, 512 threads, tile loop.
// Block x: tiles {x, x+148} (< nTiles). V staged once per block.
// Warp = (mw 0..3 -> 16 n-rows, oq 0..3 -> 32 o-cols); 32 MMA/warp/tile.
// Epilogue: acc -> padded smem -> per-warp coalesced row emit (+C).
// ---------------------------------------------------------------------------
__global__ __launch_bounds__(512)
void k_main_mma(const float* __restrict__ dists,
                float* __restrict__ out,
                int N, int T, int step, int nTiles) {
    extern __shared__ __align__(16) uint32_t smem[];
    uint32_t* sv = smem;                       // [64][SVS]  V (tf32 bits)
    uint32_t* sd = smem + AA * SVS;            // [64][SDS]  dists tile (tf32)
    float*    sa = (float*)(smem + AA * SVS + AA * SDS);   // [64][SAS] acc

    const int tid = threadIdx.x;
    const int w   = tid >> 5;
    const int l   = tid & 31;
    const int tig = l & 3;
    const int g   = l >> 2;
    const int mw  = w & 3;
    const int oq  = w >> 2;
    const int rowbase = 16 * mw;
    const int obase   = 32 * oq;

    // ---- stage V once (4 float4 per thread, coalesced) ----
    #pragma unroll
    for (int i = tid; i < AA * (D / 4); i += 512) {
        const int a  = i >> 5;
        const int o4 = (i & 31) * 4;
        const float4 v = __ldg((const float4*)&g_V[a * D + o4]);
        uint4 t;
        t.x = f2tf32(v.x); t.y = f2tf32(v.y);
        t.z = f2tf32(v.z); t.w = f2tf32(v.w);
        *(uint4*)&sv[a * SVS + o4] = t;
    }

    for (int tile = blockIdx.x; tile < nTiles; tile += gridDim.x) {
        const int n0 = tile * MT;

        // ---- stage sd (2 float4 per thread; zero-pad tail) ----
        #pragma unroll
        for (int i = tid; i < AA * (MT / 4); i += 512) {
            const int a  = i / (MT / 4);
            const int j4 = (i % (MT / 4)) * 4;
            const int n  = n0 + j4;
            const float* src = dists + (size_t)a * N + n;
            float4 v;
            if (n + 3 < N) v = __ldg((const float4*)src);
            else {
                v.x = (n + 0 < N) ? src[0] : 0.f;
                v.y = (n + 1 < N) ? src[1] : 0.f;
                v.z = (n + 2 < N) ? src[2] : 0.f;
                v.w = (n + 3 < N) ? src[3] : 0.f;
            }
            uint4 t;
            t.x = f2tf32(v.x); t.y = f2tf32(v.y);
            t.z = f2tf32(v.z); t.w = f2tf32(v.w);
            *(uint4*)&sd[a * SDS + j4] = t;
        }
        __syncthreads();   // sd ready; also: prior epilogue's sa reads done

        // ---- MMA: 8 k-steps x 4 j (o 8-col tiles) ----
        float c[4][4];
        #pragma unroll
        for (int j = 0; j < 4; j++)
            #pragma unroll
            for (int q = 0; q < 4; q++) c[j][q] = 0.f;

        #pragma unroll
        for (int ks = 0; ks < 8; ks++) {
            const int k0 = 8 * ks + tig;
            const uint32_t a0 = sd[k0 * SDS + rowbase + g];
            const uint32_t a1 = sd[k0 * SDS + rowbase + g + 8];
            const uint32_t a2 = sd[(k0 + 4) * SDS + rowbase + g];
            const uint32_t a3 = sd[(k0 + 4) * SDS + rowbase + g + 8];
            #pragma unroll
            for (int j = 0; j < 4; j++) {
                const uint32_t b0 = sv[k0 * SVS + obase + 8 * j + g];
                const uint32_t b1 = sv[(k0 + 4) * SVS + obase + 8 * j + g];
                mma_tf32(c[j][0], c[j][1], c[j][2], c[j][3],
                         a0, a1, a2, a3, b0, b1);
            }
        }
        __syncthreads();   // all sd reads done (sa may overlay semantics next)

        // ---- write accumulators to padded smem ----
        #pragma unroll
        for (int j = 0; j < 4; j++) {
            const int col = obase + 8 * j + 2 * tig;
            float2 lo; lo.x = c[j][0]; lo.y = c[j][1];
            float2 hi; hi.x = c[j][2]; hi.y = c[j][3];
            *(float2*)&sa[(rowbase + g)     * SAS + col] = lo;
            *(float2*)&sa[(rowbase + g + 8) * SAS + col] = hi;
        }
        __syncthreads();

        // ---- coalesced epilogue: warp w emits rows 4w..4w+3 ----
        #pragma unroll
        for (int r = 0; r < 4; r++) {
            const int nl = 4 * w + r;
            const int n  = n0 + nl;
            if (n < N) {
                const int t = (step * n) % T;
                const float4 av = *(const float4*)&sa[nl * SAS + 4 * l];
                const float4 cv = __ldg((const float4*)&g_C[(size_t)t * D + 4 * l]);
                float4 o;
                o.x = av.x + cv.x; o.y = av.y + cv.y;
                o.z = av.z + cv.z; o.w = av.w + cv.w;
                *(float4*)&out[(size_t)n * D + 4 * l] = o;
            }
        }
        // next loop iteration's first __syncthreads() protects sa/sd reuse
    }
}

// ---------------------------------------------------------------------------
extern "C" void kernel_launch(void* const* d_in, const int* in_sizes, int n_in,
                              void* d_out, int out_size) {
    const float* embeds = (const float*)d_in[0];   // [N, 128]
    const float* dists  = (const float*)d_in[1];   // [64, N]
    const float* W      = (const float*)d_in[2];   // [128, 256]
    const float* b      = (const float*)d_in[3];   // [128]
    const int*   anchor = (const int*)  d_in[4];   // [64] int32
    float* out = (float*)d_out;

    const int N = in_sizes[0] / D;                 // 10000

    int g = AA, y = N;                             // gcd(64, N) = 16
    while (y) { int r = g % y; g = y; y = r; }
    const int T    = N / g;                        // 625
    const int step = AA / g;                       // 4

    const int nC     = (T + RW - 1) / RW;          // 79
    const int nTiles = (N + MT - 1) / MT;          // 157
    const int smemPre = (4 * 32 * 129 + D * 8) * 4 + 12288;   // 82432 B
    const int smemMMA = (AA * SVS + AA * SDS + AA * SAS) * 4; // 87040 B

    cudaFuncSetAttribute(k_pre, cudaFuncAttributeMaxDynamicSharedMemorySize, smemPre);
    cudaFuncSetAttribute(k_main_mma, cudaFuncAttributeMaxDynamicSharedMemorySize, smemMMA);

    k_pre     <<<nC + AA / RW, 1024, smemPre>>>(embeds, W, b, anchor, N, T, nC);
    k_main_mma<<<148, 512, smemMMA>>>(dists, out, N, T, step, nTiles);
}

// round 11
// speedup vs baseline: 1.1552x; 1.1552x over previous
#include <cuda_runtime.h>
#include <cstdint>

#define D   128   // LATDIM
#define AA  64    // ANCHOR_SET_NUM
#define MT  32    // n rows per main tile -> grid 313, 2 CTAs/SM
#define RW  8     // rows per k_pre tile
#define SDS 40    // sd stride (words); 40 % 32 == 8 -> conflict-free fragments
#define SVS 136   // sv stride (words); 136 % 32 == 8
#define SAS 132   // acc stride (words)

// __device__ scratch (allocation-free rule)
__device__ float g_V[AA * D];       // [a][o]
__device__ float g_C[10048 * D];    // [t][o]

// ---------------------------------------------------------------------------
// packed f32x2 helpers (k_pre)
// ---------------------------------------------------------------------------
__device__ __forceinline__ unsigned long long pk2(float x, float y) {
    unsigned long long r;
    asm("mov.b64 %0, {%1, %2};" : "=l"(r) : "f"(x), "f"(y));
    return r;
}
__device__ __forceinline__ void unpk2(unsigned long long v, float& x, float& y) {
    asm("mov.b64 {%0, %1}, %2;" : "=f"(x), "=f"(y) : "l"(v));
}
__device__ __forceinline__ void ffma2(unsigned long long& a,
                                      unsigned long long b, unsigned long long c) {
    asm("fma.rn.f32x2 %0, %1, %2, %0;" : "+l"(a) : "l"(b), "l"(c));
}
__device__ __forceinline__ void fadd2(unsigned long long& a, unsigned long long b) {
    asm("add.rn.f32x2 %0, %0, %1;" : "+l"(a) : "l"(b));
}

// ---------------------------------------------------------------------------
// tf32 helpers (sm_80+ -> valid under compute_103)
// ---------------------------------------------------------------------------
__device__ __forceinline__ uint32_t f2tf32(float f) {
    uint32_t r;
    asm("cvt.rna.tf32.f32 %0, %1;" : "=r"(r) : "f"(f));
    return r;
}
__device__ __forceinline__ void mma_tf32(float& c0, float& c1, float& c2, float& c3,
                                         uint32_t a0, uint32_t a1, uint32_t a2,
                                         uint32_t a3, uint32_t b0, uint32_t b1) {
    asm("mma.sync.aligned.m16n8k8.row.col.f32.tf32.tf32.f32 "
        "{%0,%1,%2,%3}, {%4,%5,%6,%7}, {%8,%9}, {%0,%1,%2,%3};"
        : "+f"(c0), "+f"(c1), "+f"(c2), "+f"(c3)
        : "r"(a0), "r"(a1), "r"(a2), "r"(a3), "r"(b0), "r"(b1));
}

// ---------------------------------------------------------------------------
// k_pre (unchanged; proven R7-R10):
//   C[t][o] = (1/A) * sum_k E2[t][k] * W[o][D+k] + b[o]
//   V[a][o] = (1/A) * sum_k embeds[anchor[a]][k] * W[o][k]
// ---------------------------------------------------------------------------
__global__ __launch_bounds__(1024)
void k_pre(const float* __restrict__ embeds,
           const float* __restrict__ W,
           const float* __restrict__ b,
           const int*   __restrict__ anchor,
           int N, int T, int nC) {
    extern __shared__ __align__(16) float sm[];
    float (*Wc)[32][129] = (float(*)[32][129])sm;            // [4][32][129]
    float (*XT)[8]       = (float(*)[8])(sm + 4 * 32 * 129);
    float* sch           = sm + 4 * 32 * 129 + D * 8;        // [11][2][128]
    unsigned long long* spart = (unsigned long long*)sch;    // overlay after gemm

    const int tid  = threadIdx.x;
    const int w    = tid >> 5;
    const int l    = tid & 31;
    const bool isV = (blockIdx.x >= nC);
    const int  t0  = isV ? (blockIdx.x - nC) * RW : blockIdx.x * RW;
    const int  R   = isV ? RW : min(RW, T - t0);
    const int  woff = isV ? 0 : D;

    // stage all 4 W chunks (transposed, coalesced)
    {
        const int orow = tid >> 3;
        const int kq   = (tid & 7) * 4;
        #pragma unroll
        for (int kc = 0; kc < 4; kc++) {
            const float4 wv = __ldg((const float4*)
                &W[(size_t)orow * (2 * D) + woff + kc * 32 + kq]);
            Wc[kc][kq + 0][orow] = wv.x;
            Wc[kc][kq + 1][orow] = wv.y;
            Wc[kc][kq + 2][orow] = wv.z;
            Wc[kc][kq + 3][orow] = wv.w;
        }
    }

    // build XT[k][r]
    if (isV) {
        const int k = tid & 127, r = tid >> 7;
        XT[k][r] = __ldg(&embeds[(size_t)__ldg(&anchor[t0 + r]) * D + k]);
    } else {
        const int ch = w >> 1, half = w & 1;
        if (ch < R + 3) {
            const int rbase = 16 * (t0 + ch) + 8 * half;
            float4 acc = {0.f, 0.f, 0.f, 0.f};
            #pragma unroll
            for (int i = 0; i < 8; i++) {
                int r = rbase + i; if (r >= N) r -= N;
                const float4 v = __ldg((const float4*)&embeds[(size_t)r * D + 4 * l]);
                acc.x += v.x; acc.y += v.y; acc.z += v.z; acc.w += v.w;
            }
            *(float4*)&sch[(ch * 2 + half) * 128 + 4 * l] = acc;
        }
        __syncthreads();
        const int k = tid & 127, r = tid >> 7;
        float val = 0.f;
        if (r < R) {
            #pragma unroll
            for (int c = 0; c < 4; c++)
                val += sch[((r + c) * 2 + 0) * 128 + k]
                     + sch[((r + c) * 2 + 1) * 128 + k];
        }
        XT[k][r] = val;
    }
    __syncthreads();

    // gemm: thread (o, rq, h)
    const int o  = tid & 127;
    const int rq = (tid >> 7) & 1;
    const int h  = tid >> 8;
    unsigned long long a0 = 0ull, a1 = 0ull;

    #pragma unroll
    for (int kk = 0; kk < 32; kk++) {
        const float wv = Wc[h][kk][o];
        const ulonglong2 x = *(const ulonglong2*)&XT[h * 32 + kk][4 * rq];
        const unsigned long long ww = pk2(wv, wv);
        ffma2(a0, x.x, ww);
        ffma2(a1, x.y, ww);
    }
    __syncthreads();

    if (h > 0) {
        ulonglong2 t; t.x = a0; t.y = a1;
        *(ulonglong2*)&spart[(((h - 1) * 256) + o * 2 + rq) * 2] = t;
    }
    __syncthreads();

    if (h == 0) {
        #pragma unroll
        for (int hh = 0; hh < 3; hh++) {
            const ulonglong2 t =
                *(const ulonglong2*)&spart[((hh * 256) + o * 2 + rq) * 2];
            fadd2(a0, t.x); fadd2(a1, t.y);
        }
        float r0, r1, r2, r3;
        unpk2(a0, r0, r1); unpk2(a1, r2, r3);
        float res[4] = {r0, r1, r2, r3};
        const float sc = 1.0f / AA;
        if (isV) {
            #pragma unroll
            for (int i = 0; i < 4; i++)
                g_V[(t0 + 4 * rq + i) * D + o] = res[i] * sc;
        } else {
            const float bias = __ldg(&b[o]);
            #pragma unroll
            for (int i = 0; i < 4; i++) {
                const int row = 4 * rq + i;
                if (row < R)
                    g_C[(size_t)(t0 + row) * D + o] = res[i] * sc + bias;
            }
        }
    }
}

// ---------------------------------------------------------------------------
// k_main_mma v3: MT=32, 256 threads, grid 313 -> 2 CTAs/SM so co-resident
// blocks overlap each other's staging / MMA / epilogue phases.
// Warp = (mw 0..1 -> 16 n-rows, oq 0..3 -> 32 o-cols); 32 MMA/warp.
// ---------------------------------------------------------------------------
__global__ __launch_bounds__(256)
void k_main_mma(const float* __restrict__ dists,
                float* __restrict__ out,
                int N, int T, int step) {
    extern __shared__ __align__(16) uint32_t smem[];
    uint32_t* sv = smem;                       // [64][SVS]  V (tf32 bits)
    uint32_t* sd = smem + AA * SVS;            // [64][SDS]  dists tile (tf32)
    float*    sa = (float*)(smem + AA * SVS + AA * SDS);   // [MT][SAS] acc

    const int tid = threadIdx.x;
    const int n0  = blockIdx.x * MT;

    // ---- stage V (8 float4 per thread, coalesced row writes) ----
    #pragma unroll
    for (int i = tid; i < AA * (D / 4); i += 256) {
        const int a  = i >> 5;
        const int o4 = (i & 31) * 4;
        const float4 v = __ldg((const float4*)&g_V[a * D + o4]);
        uint4 t;
        t.x = f2tf32(v.x); t.y = f2tf32(v.y);
        t.z = f2tf32(v.z); t.w = f2tf32(v.w);
        *(uint4*)&sv[a * SVS + o4] = t;
    }

    // ---- stage sd (2 float4 per thread; zero-pad tail) ----
    #pragma unroll
    for (int i = tid; i < AA * (MT / 4); i += 256) {
        const int a  = i / (MT / 4);
        const int j4 = (i % (MT / 4)) * 4;
        const int n  = n0 + j4;
        const float* src = dists + (size_t)a * N + n;
        float4 v;
        if (n + 3 < N) v = __ldg((const float4*)src);
        else {
            v.x = (n + 0 < N) ? src[0] : 0.f;
            v.y = (n + 1 < N) ? src[1] : 0.f;
            v.z = (n + 2 < N) ? src[2] : 0.f;
            v.w = (n + 3 < N) ? src[3] : 0.f;
        }
        uint4 t;
        t.x = f2tf32(v.x); t.y = f2tf32(v.y);
        t.z = f2tf32(v.z); t.w = f2tf32(v.w);
        *(uint4*)&sd[a * SDS + j4] = t;
    }
    __syncthreads();

    const int w   = tid >> 5;
    const int l   = tid & 31;
    const int tig = l & 3;
    const int g   = l >> 2;
    const int mw  = w & 1;          // m16 tile (2 per MT=32)
    const int oq  = w >> 1;         // o-quarter
    const int rowbase = 16 * mw;
    const int obase   = 32 * oq;

    // ---- MMA: 8 k-steps x 4 j (o 8-col tiles) ----
    float c[4][4];
    #pragma unroll
    for (int j = 0; j < 4; j++)
        #pragma unroll
        for (int q = 0; q < 4; q++) c[j][q] = 0.f;

    #pragma unroll
    for (int ks = 0; ks < 8; ks++) {
        const int k0 = 8 * ks + tig;
        const uint32_t a0 = sd[k0 * SDS + rowbase + g];
        const uint32_t a1 = sd[k0 * SDS + rowbase + g + 8];
        const uint32_t a2 = sd[(k0 + 4) * SDS + rowbase + g];
        const uint32_t a3 = sd[(k0 + 4) * SDS + rowbase + g + 8];
        #pragma unroll
        for (int j = 0; j < 4; j++) {
            const uint32_t b0 = sv[k0 * SVS + obase + 8 * j + g];
            const uint32_t b1 = sv[(k0 + 4) * SVS + obase + 8 * j + g];
            mma_tf32(c[j][0], c[j][1], c[j][2], c[j][3],
                     a0, a1, a2, a3, b0, b1);
        }
    }
    __syncthreads();

    // ---- accumulators -> padded smem ----
    #pragma unroll
    for (int j = 0; j < 4; j++) {
        const int col = obase + 8 * j + 2 * tig;
        float2 lo; lo.x = c[j][0]; lo.y = c[j][1];
        float2 hi; hi.x = c[j][2]; hi.y = c[j][3];
        *(float2*)&sa[(rowbase + g)     * SAS + col] = lo;
        *(float2*)&sa[(rowbase + g + 8) * SAS + col] = hi;
    }
    __syncthreads();

    // ---- coalesced epilogue: warp w emits rows 4w..4w+3 ----
    #pragma unroll
    for (int r = 0; r < 4; r++) {
        const int nl = 4 * w + r;
        const int n  = n0 + nl;
        if (n < N) {
            const int t = (step * n) % T;
            const float4 av = *(const float4*)&sa[nl * SAS + 4 * l];
            const float4 cv = __ldg((const float4*)&g_C[(size_t)t * D + 4 * l]);
            float4 o;
            o.x = av.x + cv.x; o.y = av.y + cv.y;
            o.z = av.z + cv.z; o.w = av.w + cv.w;
            *(float4*)&out[(size_t)n * D + 4 * l] = o;
        }
    }
}

// ---------------------------------------------------------------------------
extern "C" void kernel_launch(void* const* d_in, const int* in_sizes, int n_in,
                              void* d_out, int out_size) {
    const float* embeds = (const float*)d_in[0];   // [N, 128]
    const float* dists  = (const float*)d_in[1];   // [64, N]
    const float* W      = (const float*)d_in[2];   // [128, 256]
    const float* b      = (const float*)d_in[3];   // [128]
    const int*   anchor = (const int*)  d_in[4];   // [64] int32
    float* out = (float*)d_out;

    const int N = in_sizes[0] / D;                 // 10000

    int g = AA, y = N;                             // gcd(64, N) = 16
    while (y) { int r = g % y; g = y; y = r; }
    const int T    = N / g;                        // 625
    const int step = AA / g;                       // 4

    const int nC     = (T + RW - 1) / RW;          // 79
    const int nTiles = (N + MT - 1) / MT;          // 313
    const int smemPre = (4 * 32 * 129 + D * 8) * 4 + 12288;       // 82432 B
    const int smemMMA = (AA * SVS + AA * SDS + MT * SAS) * 4;     // 61952 B

    cudaFuncSetAttribute(k_pre, cudaFuncAttributeMaxDynamicSharedMemorySize, smemPre);
    cudaFuncSetAttribute(k_main_mma, cudaFuncAttributeMaxDynamicSharedMemorySize, smemMMA);

    k_pre     <<<nC + AA / RW, 1024, smemPre>>>(embeds, W, b, anchor, N, T, nC);
    k_main_mma<<<nTiles, 256, smemMMA>>>(dists, out, N, T, step);
}

// round 12
// speedup vs baseline: 1.1577x; 1.0022x over previous
#include <cuda_runtime.h>
#include <cstdint>

#define D    128   // LATDIM
#define AA   64    // ANCHOR_SET_NUM
#define MT   48    // n rows per main tile -> 209 consumer blocks
#define RW   8     // rows per k_pre tile (79 C blocks + 8 V blocks)
#define NPRE 87    // producer blocks
#define SDS  72    // sd stride (words); 72 % 32 == 8 -> conflict-free fragments
#define SVS  136   // sv stride (words); 136 % 32 == 8
#define SAS  132   // acc stride (words)

// __device__ scratch (allocation-free rule)
__device__ float g_V[AA * D];       // [a][o]
__device__ float g_C[10048 * D];    // [t][o]
__device__ unsigned g_vCnt = 0, g_cCnt = 0, g_doneCnt = 0;

// ---------------------------------------------------------------------------
// packed f32x2 helpers (producer gemm)
// ---------------------------------------------------------------------------
__device__ __forceinline__ unsigned long long pk2(float x, float y) {
    unsigned long long r;
    asm("mov.b64 %0, {%1, %2};" : "=l"(r) : "f"(x), "f"(y));
    return r;
}
__device__ __forceinline__ void unpk2(unsigned long long v, float& x, float& y) {
    asm("mov.b64 {%0, %1}, %2;" : "=f"(x), "=f"(y) : "l"(v));
}
__device__ __forceinline__ void ffma2(unsigned long long& a,
                                      unsigned long long b, unsigned long long c) {
    asm("fma.rn.f32x2 %0, %1, %2, %0;" : "+l"(a) : "l"(b), "l"(c));
}
__device__ __forceinline__ void fadd2(unsigned long long& a, unsigned long long b) {
    asm("add.rn.f32x2 %0, %0, %1;" : "+l"(a) : "l"(b));
}

// ---------------------------------------------------------------------------
// tf32 helpers (sm_80+ -> valid under compute_103)
// ---------------------------------------------------------------------------
__device__ __forceinline__ uint32_t f2tf32(float f) {
    uint32_t r;
    asm("cvt.rna.tf32.f32 %0, %1;" : "=r"(r) : "f"(f));
    return r;
}
__device__ __forceinline__ void mma_tf32(float& c0, float& c1, float& c2, float& c3,
                                         uint32_t a0, uint32_t a1, uint32_t a2,
                                         uint32_t a3, uint32_t b0, uint32_t b1) {
    asm("mma.sync.aligned.m16n8k8.row.col.f32.tf32.tf32.f32 "
        "{%0,%1,%2,%3}, {%4,%5,%6,%7}, {%8,%9}, {%0,%1,%2,%3};"
        : "+f"(c0), "+f"(c1), "+f"(c2), "+f"(c3)
        : "r"(a0), "r"(a1), "r"(a2), "r"(a3), "r"(b0), "r"(b1));
}

// flag wait (consumer side; producers never wait -> deadlock-free)
__device__ __forceinline__ void wait_cnt(volatile unsigned* c, unsigned tgt) {
    while (*c < tgt) __nanosleep(64);
    __threadfence();
}

// ---------------------------------------------------------------------------
// fused kernel: 1024 threads, grid 296 (= 2 x 148, fully co-resident).
// bids [0, NPRE): producer role (exact proven k_pre body + release flag)
// bids [NPRE, ..): consumer role (tf32 mma.sync main GEMM + C epilogue)
// ---------------------------------------------------------------------------
__global__ __launch_bounds__(1024)
void fused(const float* __restrict__ embeds,
           const float* __restrict__ dists,
           const float* __restrict__ W,
           const float* __restrict__ b,
           const int*   __restrict__ anchor,
           float* __restrict__ out,
           int N, int T, int step, int nC, int nMain) {
    extern __shared__ __align__(16) float sm[];
    const int tid = threadIdx.x;

    if (blockIdx.x < (unsigned)NPRE) {
        // ================= PRODUCER (proven k_pre body) =================
        float (*Wc)[32][129] = (float(*)[32][129])sm;            // [4][32][129]
        float (*XT)[8]       = (float(*)[8])(sm + 4 * 32 * 129);
        float* sch           = sm + 4 * 32 * 129 + D * 8;        // [11][2][128]
        unsigned long long* spart = (unsigned long long*)sch;

        const int w    = tid >> 5;
        const int l    = tid & 31;
        const bool isV = ((int)blockIdx.x >= nC);
        const int  t0  = isV ? (blockIdx.x - nC) * RW : blockIdx.x * RW;
        const int  R   = isV ? RW : min(RW, T - t0);
        const int  woff = isV ? 0 : D;

        {   // stage all 4 W chunks (transposed, coalesced)
            const int orow = tid >> 3;
            const int kq   = (tid & 7) * 4;
            #pragma unroll
            for (int kc = 0; kc < 4; kc++) {
                const float4 wv = __ldg((const float4*)
                    &W[(size_t)orow * (2 * D) + woff + kc * 32 + kq]);
                Wc[kc][kq + 0][orow] = wv.x;
                Wc[kc][kq + 1][orow] = wv.y;
                Wc[kc][kq + 2][orow] = wv.z;
                Wc[kc][kq + 3][orow] = wv.w;
            }
        }

        if (isV) {
            const int k = tid & 127, r = tid >> 7;
            XT[k][r] = __ldg(&embeds[(size_t)__ldg(&anchor[t0 + r]) * D + k]);
        } else {
            const int ch = w >> 1, half = w & 1;
            if (ch < R + 3) {
                const int rbase = 16 * (t0 + ch) + 8 * half;
                float4 acc = {0.f, 0.f, 0.f, 0.f};
                #pragma unroll
                for (int i = 0; i < 8; i++) {
                    int r = rbase + i; if (r >= N) r -= N;
                    const float4 v = __ldg((const float4*)&embeds[(size_t)r * D + 4 * l]);
                    acc.x += v.x; acc.y += v.y; acc.z += v.z; acc.w += v.w;
                }
                *(float4*)&sch[(ch * 2 + half) * 128 + 4 * l] = acc;
            }
            __syncthreads();
            const int k = tid & 127, r = tid >> 7;
            float val = 0.f;
            if (r < R) {
                #pragma unroll
                for (int c = 0; c < 4; c++)
                    val += sch[((r + c) * 2 + 0) * 128 + k]
                         + sch[((r + c) * 2 + 1) * 128 + k];
            }
            XT[k][r] = val;
        }
        __syncthreads();

        const int o  = tid & 127;
        const int rq = (tid >> 7) & 1;
        const int h  = tid >> 8;
        unsigned long long a0 = 0ull, a1 = 0ull;

        #pragma unroll
        for (int kk = 0; kk < 32; kk++) {
            const float wv = Wc[h][kk][o];
            const ulonglong2 x = *(const ulonglong2*)&XT[h * 32 + kk][4 * rq];
            const unsigned long long ww = pk2(wv, wv);
            ffma2(a0, x.x, ww);
            ffma2(a1, x.y, ww);
        }
        __syncthreads();

        if (h > 0) {
            ulonglong2 t; t.x = a0; t.y = a1;
            *(ulonglong2*)&spart[(((h - 1) * 256) + o * 2 + rq) * 2] = t;
        }
        __syncthreads();

        if (h == 0) {
            #pragma unroll
            for (int hh = 0; hh < 3; hh++) {
                const ulonglong2 t =
                    *(const ulonglong2*)&spart[((hh * 256) + o * 2 + rq) * 2];
                fadd2(a0, t.x); fadd2(a1, t.y);
            }
            float r0, r1, r2, r3;
            unpk2(a0, r0, r1); unpk2(a1, r2, r3);
            float res[4] = {r0, r1, r2, r3};
            const float sc = 1.0f / AA;
            if (isV) {
                #pragma unroll
                for (int i = 0; i < 4; i++)
                    g_V[(t0 + 4 * rq + i) * D + o] = res[i] * sc;
            } else {
                const float bias = __ldg(&b[o]);
                #pragma unroll
                for (int i = 0; i < 4; i++) {
                    const int row = 4 * rq + i;
                    if (row < R)
                        g_C[(size_t)(t0 + row) * D + o] = res[i] * sc + bias;
                }
            }
        }

        // release flag
        __syncthreads();
        if (tid == 0) {
            __threadfence();
            atomicAdd(isV ? &g_vCnt : &g_cCnt, 1u);
        }
        return;
    }

    // ================= CONSUMER (main GEMM tile) =================
    uint32_t* sv = (uint32_t*)sm;                  // [64][SVS]
    uint32_t* sd = (uint32_t*)sm + AA * SVS;       // [64][SDS]
    float*    sa = sm + AA * SVS + AA * SDS;       // [MT][SAS]

    const int n0 = (blockIdx.x - NPRE) * MT;

    // stage sd early (DRAM; overlaps producers). 768 float4 -> tid<768.
    if (tid < AA * (MT / 4)) {
        const int a  = tid / (MT / 4);
        const int j4 = (tid % (MT / 4)) * 4;
        const int n  = n0 + j4;
        const float* src = dists + (size_t)a * N + n;
        float4 v;
        if (n + 3 < N) v = __ldg((const float4*)src);
        else {
            v.x = (n + 0 < N) ? src[0] : 0.f;
            v.y = (n + 1 < N) ? src[1] : 0.f;
            v.z = (n + 2 < N) ? src[2] : 0.f;
            v.w = (n + 3 < N) ? src[3] : 0.f;
        }
        uint4 t;
        t.x = f2tf32(v.x); t.y = f2tf32(v.y);
        t.z = f2tf32(v.z); t.w = f2tf32(v.w);
        *(uint4*)&sd[a * SDS + j4] = t;
    }

    // wait for V
    if (tid == 0) wait_cnt(&g_vCnt, NPRE - (unsigned)nC);   // 8 V blocks
    __syncthreads();

    // stage sv from g_V (plain loads; written this launch by producers)
    #pragma unroll
    for (int i = tid; i < AA * (D / 4); i += 1024) {
        const int a  = i >> 5;
        const int o4 = (i & 31) * 4;
        const float4 v = *(const float4*)&g_V[a * D + o4];
        uint4 t;
        t.x = f2tf32(v.x); t.y = f2tf32(v.y);
        t.z = f2tf32(v.z); t.w = f2tf32(v.w);
        *(uint4*)&sv[a * SVS + o4] = t;
    }
    __syncthreads();

    const int w = tid >> 5;
    if (w >= 12) return;              // warps 12..31 done (helped staging)

    const int l   = tid & 31;
    const int tig = l & 3;
    const int g   = l >> 2;
    const int mw  = w % 3;            // m16 tile (3 per MT=48)
    const int oq  = w / 3;            // o-quarter (32 cols)
    const int rowbase = 16 * mw;
    const int obase   = 32 * oq;

    float c[4][4];
    #pragma unroll
    for (int j = 0; j < 4; j++)
        #pragma unroll
        for (int q = 0; q < 4; q++) c[j][q] = 0.f;

    #pragma unroll
    for (int ks = 0; ks < 8; ks++) {
        const int k0 = 8 * ks + tig;
        const uint32_t a0 = sd[k0 * SDS + rowbase + g];
        const uint32_t a1 = sd[k0 * SDS + rowbase + g + 8];
        const uint32_t a2 = sd[(k0 + 4) * SDS + rowbase + g];
        const uint32_t a3 = sd[(k0 + 4) * SDS + rowbase + g + 8];
        #pragma unroll
        for (int j = 0; j < 4; j++) {
            const uint32_t b0 = sv[k0 * SVS + obase + 8 * j + g];
            const uint32_t b1 = sv[(k0 + 4) * SVS + obase + 8 * j + g];
            mma_tf32(c[j][0], c[j][1], c[j][2], c[j][3],
                     a0, a1, a2, a3, b0, b1);
        }
    }

    // accumulators -> padded smem
    #pragma unroll
    for (int j = 0; j < 4; j++) {
        const int col = obase + 8 * j + 2 * tig;
        float2 lo; lo.x = c[j][0]; lo.y = c[j][1];
        float2 hi; hi.x = c[j][2]; hi.y = c[j][3];
        *(float2*)&sa[(rowbase + g)     * SAS + col] = lo;
        *(float2*)&sa[(rowbase + g + 8) * SAS + col] = hi;
    }
    asm volatile("bar.sync 1, 384;" ::: "memory");

    // wait for C
    if (tid == 0) wait_cnt(&g_cCnt, (unsigned)nC);
    asm volatile("bar.sync 1, 384;" ::: "memory");

    // coalesced epilogue: warp w emits rows 4w..4w+3
    #pragma unroll
    for (int r = 0; r < 4; r++) {
        const int nl = 4 * w + r;
        const int n  = n0 + nl;
        if (n < N) {
            const int t = (step * n) % T;
            const float4 av = *(const float4*)&sa[nl * SAS + 4 * l];
            const float4 cv = *(const float4*)&g_C[(size_t)t * D + 4 * l];
            float4 o;
            o.x = av.x + cv.x; o.y = av.y + cv.y;
            o.z = av.z + cv.z; o.w = av.w + cv.w;
            *(float4*)&out[(size_t)n * D + 4 * l] = o;
        }
    }

    // done-count; last consumer resets flags for the next graph replay
    asm volatile("bar.sync 1, 384;" ::: "memory");
    if (tid == 0) {
        const unsigned fin = atomicAdd(&g_doneCnt, 1u);
        if (fin == (unsigned)nMain - 1u) {
            g_vCnt = 0; g_cCnt = 0; g_doneCnt = 0;
            __threadfence();
        }
    }
}

// ---------------------------------------------------------------------------
extern "C" void kernel_launch(void* const* d_in, const int* in_sizes, int n_in,
                              void* d_out, int out_size) {
    const float* embeds = (const float*)d_in[0];   // [N, 128]
    const float* dists  = (const float*)d_in[1];   // [64, N]
    const float* W      = (const float*)d_in[2];   // [128, 256]
    const float* b      = (const float*)d_in[3];   // [128]
    const int*   anchor = (const int*)  d_in[4];   // [64] int32
    float* out = (float*)d_out;

    const int N = in_sizes[0] / D;                 // 10000

    int g = AA, y = N;                             // gcd(64, N) = 16
    while (y) { int r = g % y; g = y; y = r; }
    const int T    = N / g;                        // 625
    const int step = AA / g;                       // 4

    const int nC    = (T + RW - 1) / RW;           // 79
    const int nMain = (N + MT - 1) / MT;           // 209
    const int grid  = NPRE + nMain;                // 296 = 2 x 148

    const int smemPre  = (4 * 32 * 129 + D * 8) * 4 + 12288;   // 82432 B
    const int smemMain = (AA * SVS + AA * SDS + MT * SAS) * 4; // 78592 B
    const int smemDyn  = smemPre > smemMain ? smemPre : smemMain;

    cudaFuncSetAttribute(fused, cudaFuncAttributeMaxDynamicSharedMemorySize, smemDyn);

    fused<<<grid, 1024, smemDyn>>>(embeds, dists, W, b, anchor, out,
                                   N, T, step, nC, nMain);
}